// round 15
// baseline (speedup 1.0000x reference)
#include <cuda_runtime.h>
#include <math.h>

// Problem constants
constexpr int CB = 512;        // batch
constexpr int CK = 25;         // nodes per board (incl. anchor node 0)
constexpr int CH = 256;        // hidden
constexpr int CSTEPS = 32;
constexpr int CN = CB * CK;    // 12800 nodes
constexpr int CNH = CN * CH;   // 3276800

// Scratch (device globals; no allocation allowed)
__device__ float g_x[CNH];             // lstm_emb (constant x)
__device__ float g_h[CNH];             // hidden state
__device__ float g_c[CNH];             // cell state
__device__ float g_gx[CN * 1024];      // chain prefix: x @ W_ih[:, :256].T
__device__ float g_A[CNH];             // per-step A = h @ W1^T
__device__ float g_m[CNH];             // per-step messages
__device__ float g_t2[CN * 1024];      // per-step t2 = h @ W_hh^T
__device__ float g_gates[CN * 1024];   // gates
__device__ float g_W2P[256 * 256];     // W2 pair-packed: (k-pair, rh) -> 2x u64 lanes
__device__ float g_oe[CNH];            // output_embeddings
__device__ float g_red[CSTEPS * CB + CB];  // per-block gol partials

// ---------------------------------------------------------------------------
// Packed f32x2 helpers (Blackwell FFMA2) — bitwise identical per lane to scalar.
typedef unsigned long long u64;
__device__ __forceinline__ u64 pk2(float lo, float hi)
{
    u64 r; asm("mov.b64 %0, {%1, %2};" : "=l"(r) : "f"(lo), "f"(hi)); return r;
}
__device__ __forceinline__ float2 up2(u64 v)
{
    float2 f; asm("mov.b64 {%0, %1}, %2;" : "=f"(f.x), "=f"(f.y) : "l"(v)); return f;
}
__device__ __forceinline__ u64 ffma2(u64 a, u64 b, u64 c)
{
    u64 d; asm("fma.rn.f32x2 %0, %1, %2, %3;" : "=l"(d) : "l"(a), "l"(b), "l"(c));
    return d;
}

// ---------------------------------------------------------------------------
// XLA elementwise replicas (EmitFastTanh; logistic = 0.5 + 0.5*tanh(0.5x)).
__device__ __forceinline__ float xla_tanh(float x)
{
    float xc = fminf(fmaxf(x, -9.f), 9.f);
    float x2 = __fmul_rn(xc, xc);
    float np = fmaf(x2, -2.76076847742355e-16f, 2.00018790482477e-13f);
    np = fmaf(x2, np, -8.60467152213735e-11f);
    np = fmaf(x2, np,  5.12229709037114e-08f);
    np = fmaf(x2, np,  1.48572235717979e-05f);
    np = fmaf(x2, np,  6.37261928875436e-04f);
    np = fmaf(x2, np,  4.89352455891786e-03f);
    float num = __fmul_rn(xc, np);
    float dp = fmaf(x2, 1.19825839466702e-06f, 1.18534705686654e-04f);
    dp = fmaf(x2, dp, 2.26843463243900e-03f);
    dp = fmaf(x2, dp, 4.89352518554385e-03f);
    float r = __fdiv_rn(num, dp);
    return (fabsf(x) < 0.0004f) ? x : r;
}
__device__ __forceinline__ float xla_sigmoid(float x)
{
    return __fadd_rn(0.5f, __fmul_rn(0.5f, xla_tanh(__fmul_rn(0.5f, x))));
}

// ---------------------------------------------------------------------------
// W2 pair-packed layout for one-LDG.128-per-2k in msg_exact:
//   float offset of (k, rh, lane) = ((k>>1)*128 + rh)*4 + (k&1)*2 + lane
//   lane 0 -> output r=2rh, lane 1 -> r=2rh+1;  W2[r][k] = Wmsg[r*512+256+k]
__global__ void prep_kernel(const float* __restrict__ Wmsg)
{
    int t = blockIdx.x * blockDim.x + threadIdx.x;
    if (t >= 256 * 128) return;
    int k = t >> 7, rh = t & 127;
    size_t off = ((size_t)(k >> 1) * 128 + rh) * 4 + (k & 1) * 2;
    g_W2P[off]     = Wmsg[(2 * rh)     * 512 + 256 + k];
    g_W2P[off + 1] = Wmsg[(2 * rh + 1) * 512 + 256 + k];
}

// ---------------------------------------------------------------------------
__global__ void gather_init(const float* __restrict__ emb,
                            const int* __restrict__ perm,
                            float* __restrict__ out_lstm_emb)
{
    int gid = blockIdx.x * blockDim.x + threadIdx.x;
    if (gid >= CNH) return;
    int n = gid >> 8, h = gid & 255;
    float v = emb[(size_t)perm[n] * CH + h];
    g_x[gid] = v;
    out_lstm_emb[gid] = v;
    g_h[gid] = v;
    g_c[gid] = v;
    if (n % CK == 0) g_m[gid] = 0.f;   // node 0 never receives messages
}

// ---------------------------------------------------------------------------
// 256-thread GEMM tile (128x128 @ (by,bx)) of A[M,K] @ B[N,K]^T.
// One sequential fma chain over ascending k per output; FFMA2 lanes bitwise
// == scalar. M-paired accumulators; register double-buffered smem pipeline.
// Cinit != null : acc starts at Cinit (chain prefix).
// Cadd  != null : post-add (commutative).
__device__ __forceinline__ void sgemm_tile(
    int K,
    const float* __restrict__ A, int lda,
    const float* __restrict__ Bm, int ldb,
    float* __restrict__ C, int ldc,
    const float* __restrict__ Cinit,
    const float* __restrict__ Cadd,
    int bx, int by,
    float As[2][16][128], float Bs[2][16][128])
{
    const int tid = threadIdx.x;
    const int tx = tid & 15;
    const int ty = tid >> 4;
    const float* Ab = A + (size_t)by * 128 * lda;
    const float* Bb = Bm + (size_t)bx * 128 * ldb;
    const int lrow = tid >> 1;
    const int lk4b = (tid & 1) * 2;

    u64 acc2[4][8];   // [m-pair][j]; lanes = (row m0, row m1)
    if (Cinit) {
#pragma unroll
        for (int mp = 0; mp < 4; mp++) {
            int lr0 = (mp < 2) ? (ty * 4 + mp * 2) : (64 + ty * 4 + (mp - 2) * 2);
            size_t r0 = (size_t)by * 128 + lr0;
            const float* I0 = Cinit + r0 * ldc + (size_t)bx * 128;
            const float* I1 = I0 + ldc;
            float4 a0 = *(const float4*)(I0 + tx * 4);
            float4 a1 = *(const float4*)(I0 + 64 + tx * 4);
            float4 b0 = *(const float4*)(I1 + tx * 4);
            float4 b1 = *(const float4*)(I1 + 64 + tx * 4);
            acc2[mp][0] = pk2(a0.x, b0.x); acc2[mp][1] = pk2(a0.y, b0.y);
            acc2[mp][2] = pk2(a0.z, b0.z); acc2[mp][3] = pk2(a0.w, b0.w);
            acc2[mp][4] = pk2(a1.x, b1.x); acc2[mp][5] = pk2(a1.y, b1.y);
            acc2[mp][6] = pk2(a1.z, b1.z); acc2[mp][7] = pk2(a1.w, b1.w);
        }
    } else {
#pragma unroll
        for (int mp = 0; mp < 4; mp++)
#pragma unroll
            for (int j = 0; j < 8; j++) acc2[mp][j] = 0ull;
    }

    float4 avs[2], bvs[2];
#pragma unroll
    for (int u = 0; u < 2; u++) {
        int k4 = lk4b + u;
        avs[u] = *(const float4*)(Ab + (size_t)lrow * lda + k4 * 4);
        bvs[u] = *(const float4*)(Bb + (size_t)lrow * ldb + k4 * 4);
    }
#pragma unroll
    for (int u = 0; u < 2; u++) {
        int k4 = lk4b + u;
        As[0][k4 * 4 + 0][lrow] = avs[u].x;
        As[0][k4 * 4 + 1][lrow] = avs[u].y;
        As[0][k4 * 4 + 2][lrow] = avs[u].z;
        As[0][k4 * 4 + 3][lrow] = avs[u].w;
        Bs[0][k4 * 4 + 0][lrow] = bvs[u].x;
        Bs[0][k4 * 4 + 1][lrow] = bvs[u].y;
        Bs[0][k4 * 4 + 2][lrow] = bvs[u].z;
        Bs[0][k4 * 4 + 3][lrow] = bvs[u].w;
    }
    __syncthreads();

    const int T = K >> 4;
    int buf = 0;
    for (int t = 0; t < T; t++) {
        if (t + 1 < T) {
            int kt = (t + 1) * 16;
#pragma unroll
            for (int u = 0; u < 2; u++) {
                int k4 = lk4b + u;
                avs[u] = *(const float4*)(Ab + (size_t)lrow * lda + kt + k4 * 4);
                bvs[u] = *(const float4*)(Bb + (size_t)lrow * ldb + kt + k4 * 4);
            }
        }
#pragma unroll
        for (int k = 0; k < 16; k++) {
            u64 ap[4];
            ap[0] = *(const u64*)(&As[buf][k][ty * 4]);
            ap[1] = *(const u64*)(&As[buf][k][ty * 4 + 2]);
            ap[2] = *(const u64*)(&As[buf][k][64 + ty * 4]);
            ap[3] = *(const u64*)(&As[buf][k][64 + ty * 4 + 2]);
            float b[8];
            *(float4*)(b)     = *(const float4*)(&Bs[buf][k][tx * 4]);
            *(float4*)(b + 4) = *(const float4*)(&Bs[buf][k][64 + tx * 4]);
#pragma unroll
            for (int j = 0; j < 8; j++) {
                u64 bd = pk2(b[j], b[j]);
#pragma unroll
                for (int mp = 0; mp < 4; mp++)
                    acc2[mp][j] = ffma2(ap[mp], bd, acc2[mp][j]);
            }
        }
        if (t + 1 < T) {
            int nb = buf ^ 1;
#pragma unroll
            for (int u = 0; u < 2; u++) {
                int k4 = lk4b + u;
                As[nb][k4 * 4 + 0][lrow] = avs[u].x;
                As[nb][k4 * 4 + 1][lrow] = avs[u].y;
                As[nb][k4 * 4 + 2][lrow] = avs[u].z;
                As[nb][k4 * 4 + 3][lrow] = avs[u].w;
                Bs[nb][k4 * 4 + 0][lrow] = bvs[u].x;
                Bs[nb][k4 * 4 + 1][lrow] = bvs[u].y;
                Bs[nb][k4 * 4 + 2][lrow] = bvs[u].z;
                Bs[nb][k4 * 4 + 3][lrow] = bvs[u].w;
            }
            __syncthreads();
            buf = nb;
        }
    }

#pragma unroll
    for (int mp = 0; mp < 4; mp++) {
        int lr0 = (mp < 2) ? (ty * 4 + mp * 2) : (64 + ty * 4 + (mp - 2) * 2);
        size_t r0 = (size_t)by * 128 + lr0;
        float* C0 = C + r0 * ldc + (size_t)bx * 128;
        float* C1 = C0 + ldc;
        float2 p[8];
#pragma unroll
        for (int j = 0; j < 8; j++) p[j] = up2(acc2[mp][j]);
        float4 v00 = make_float4(p[0].x, p[1].x, p[2].x, p[3].x);
        float4 v01 = make_float4(p[4].x, p[5].x, p[6].x, p[7].x);
        float4 v10 = make_float4(p[0].y, p[1].y, p[2].y, p[3].y);
        float4 v11 = make_float4(p[4].y, p[5].y, p[6].y, p[7].y);
        if (Cadd) {
            const float* A0 = Cadd + r0 * ldc + (size_t)bx * 128;
            const float* A1 = A0 + ldc;
            float4 c00 = *(const float4*)(A0 + tx * 4);
            float4 c01 = *(const float4*)(A0 + 64 + tx * 4);
            float4 c10 = *(const float4*)(A1 + tx * 4);
            float4 c11 = *(const float4*)(A1 + 64 + tx * 4);
            v00.x = __fadd_rn(v00.x, c00.x); v00.y = __fadd_rn(v00.y, c00.y);
            v00.z = __fadd_rn(v00.z, c00.z); v00.w = __fadd_rn(v00.w, c00.w);
            v01.x = __fadd_rn(v01.x, c01.x); v01.y = __fadd_rn(v01.y, c01.y);
            v01.z = __fadd_rn(v01.z, c01.z); v01.w = __fadd_rn(v01.w, c01.w);
            v10.x = __fadd_rn(v10.x, c10.x); v10.y = __fadd_rn(v10.y, c10.y);
            v10.z = __fadd_rn(v10.z, c10.z); v10.w = __fadd_rn(v10.w, c10.w);
            v11.x = __fadd_rn(v11.x, c11.x); v11.y = __fadd_rn(v11.y, c11.y);
            v11.z = __fadd_rn(v11.z, c11.z); v11.w = __fadd_rn(v11.w, c11.w);
        }
        *(float4*)(C0 + tx * 4) = v00;
        *(float4*)(C0 + 64 + tx * 4) = v01;
        *(float4*)(C1 + tx * 4) = v10;
        *(float4*)(C1 + 64 + tx * 4) = v11;
    }
}

__global__ __launch_bounds__(256, 2) void sgemm_nt(
    int K,
    const float* __restrict__ A, int lda,
    const float* __restrict__ Bm, int ldb,
    float* __restrict__ C, int ldc,
    const float* __restrict__ Cinit,
    const float* __restrict__ Cadd)
{
    __shared__ float As[2][16][128];
    __shared__ float Bs[2][16][128];
    sgemm_tile(K, A, lda, Bm, ldb, C, ldc, Cinit, Cadd,
               blockIdx.x, blockIdx.y, As, Bs);
}

// Fused pre-msg launch: blocks 0..799 compute t2 = h @ W_hh^T,
// blocks 800..999 compute A = h @ W1^T. Both depend only on h.
__global__ __launch_bounds__(256, 2) void step_pre(
    const float* __restrict__ Whh, const float* __restrict__ Wmsg)
{
    __shared__ float As[2][16][128];
    __shared__ float Bs[2][16][128];
    int bid = blockIdx.x;
    if (bid < 800) {
        sgemm_tile(256, g_h, 256, Whh, 256, g_t2, 1024, nullptr, nullptr,
                   bid & 7, bid >> 3, As, Bs);
    } else {
        int i = bid - 800;
        sgemm_tile(256, g_h, 256, Wmsg, 512, g_A, 256, nullptr, nullptr,
                   i & 1, i >> 1, As, Bs);
    }
}

// ---------------------------------------------------------------------------
// Exact per-edge msg chains, FFMA2, paired-k inner loop, TWO dsts per block:
// block (jp, b) handles j0 = jp and j1 = jp+12 of board b. The A_i seed is
// dst-independent (loaded once, seeds both chains); W2P is loaded once per
// 2 k's and feeds both dst chains -> LDG traffic halves, issue overhead
// drops to 99/96 slots. Chain per output r is unchanged: acc = A_i[r],
// ascending k (k, k+1), ascending-i sum with i != j — bitwise identical.
__global__ __launch_bounds__(128) void msg_exact()
{
    __shared__ u64 hj2[2][256];            // duplicated lanes per dst
    const int j0 = blockIdx.x;             // 0..11
    const int j1 = j0 + 12;
    const int b = blockIdx.y;
    const int base = b * CK + 1;
    const int rh = threadIdx.x;

    {
        float v0 = g_h[(size_t)(base + j0) * CH + rh];
        float v1 = g_h[(size_t)(base + j0) * CH + rh + 128];
        hj2[0][rh] = pk2(v0, v0);
        hj2[0][rh + 128] = pk2(v1, v1);
        float w0 = g_h[(size_t)(base + j1) * CH + rh];
        float w1 = g_h[(size_t)(base + j1) * CH + rh + 128];
        hj2[1][rh] = pk2(w0, w0);
        hj2[1][rh + 128] = pk2(w1, w1);
    }
    __syncthreads();

    u64 acc0[24], acc1[24];
#pragma unroll
    for (int i = 0; i < 24; i++) {
        u64 a = *(const u64*)(&g_A[(size_t)(base + i) * CH + 2 * rh]);
        acc0[i] = a;
        acc1[i] = a;
    }

    const ulonglong2* wp = (const ulonglong2*)g_W2P + rh;
    for (int kp = 0; kp < 128; kp++) {
        ulonglong2 w = wp[(size_t)kp * 128];
        ulonglong2 h0 = *(const ulonglong2*)(&hj2[0][2 * kp]);
        ulonglong2 h1 = *(const ulonglong2*)(&hj2[1][2 * kp]);
#pragma unroll
        for (int i = 0; i < 24; i++) {
            acc0[i] = ffma2(h0.x, w.x, acc0[i]);   // k = 2kp
            acc0[i] = ffma2(h0.y, w.y, acc0[i]);   // k = 2kp+1
            acc1[i] = ffma2(h1.x, w.x, acc1[i]);
            acc1[i] = ffma2(h1.y, w.y, acc1[i]);
        }
    }

    {
        float mlo = 0.f, mhi = 0.f;
#pragma unroll
        for (int i = 0; i < 24; i++)
            if (i != j0) {
                float2 e = up2(acc0[i]);
                mlo = __fadd_rn(mlo, fmaxf(e.x, 0.f));
                mhi = __fadd_rn(mhi, fmaxf(e.y, 0.f));
            }
        *(float2*)(&g_m[(size_t)(base + j0) * CH + 2 * rh]) = make_float2(mlo, mhi);
    }
    {
        float mlo = 0.f, mhi = 0.f;
#pragma unroll
        for (int i = 0; i < 24; i++)
            if (i != j1) {
                float2 e = up2(acc1[i]);
                mlo = __fadd_rn(mlo, fmaxf(e.x, 0.f));
                mhi = __fadd_rn(mhi, fmaxf(e.y, 0.f));
            }
        *(float2*)(&g_m[(size_t)(base + j1) * CH + 2 * rh]) = make_float2(mlo, mhi);
    }
}

// ---------------------------------------------------------------------------
// LSTM pointwise, float4-vectorized on internal buffers; scalar stores to the
// (4B-aligned) output slice.
__global__ void lstm_step(float* __restrict__ hs_slice)
{
    int t = blockIdx.x * blockDim.x + threadIdx.x;
    if (t >= CNH / 4) return;
    int n = t >> 6;
    int h4 = t & 63;
    const float4* g = (const float4*)(g_gates + (size_t)n * 1024);
    float4 ig = g[h4], fg = g[64 + h4], gg = g[128 + h4], og = g[192 + h4];
    float4 c = *(const float4*)(g_c + (size_t)t * 4);
    float4 nc, nh;
    {
        float si = xla_sigmoid(ig.x), sf = xla_sigmoid(fg.x), so = xla_sigmoid(og.x);
        nc.x = __fadd_rn(__fmul_rn(sf, c.x), __fmul_rn(si, xla_tanh(gg.x)));
        nh.x = __fmul_rn(so, xla_tanh(nc.x));
    }
    {
        float si = xla_sigmoid(ig.y), sf = xla_sigmoid(fg.y), so = xla_sigmoid(og.y);
        nc.y = __fadd_rn(__fmul_rn(sf, c.y), __fmul_rn(si, xla_tanh(gg.y)));
        nh.y = __fmul_rn(so, xla_tanh(nc.y));
    }
    {
        float si = xla_sigmoid(ig.z), sf = xla_sigmoid(fg.z), so = xla_sigmoid(og.z);
        nc.z = __fadd_rn(__fmul_rn(sf, c.z), __fmul_rn(si, xla_tanh(gg.z)));
        nh.z = __fmul_rn(so, xla_tanh(nc.z));
    }
    {
        float si = xla_sigmoid(ig.w), sf = xla_sigmoid(fg.w), so = xla_sigmoid(og.w);
        nc.w = __fadd_rn(__fmul_rn(sf, c.w), __fmul_rn(si, xla_tanh(gg.w)));
        nh.w = __fmul_rn(so, xla_tanh(nc.w));
    }
    *(float4*)(g_c + (size_t)t * 4) = nc;
    *(float4*)(g_h + (size_t)t * 4) = nh;
    float* hp = hs_slice + (size_t)t * 4;
    hp[0] = nh.x; hp[1] = nh.y; hp[2] = nh.z; hp[3] = nh.w;
}

// ---------------------------------------------------------------------------
__global__ void finalize_emb(float* __restrict__ o_in, float* __restrict__ o_out)
{
    int gid = blockIdx.x * blockDim.x + threadIdx.x;
    if (gid >= CNH) return;
    int n = gid >> 8;
    bool anchor = (n % CK) == 0;
    float xv = g_x[gid];
    float hv = g_h[gid];
    float ov = g_oe[gid];
    o_in[gid]  = anchor ? xv : hv;
    o_out[gid] = anchor ? xv : ov;
}

// ---------------------------------------------------------------------------
__global__ __launch_bounds__(256) void gol_kernel(const float* __restrict__ src, int out_base)
{
    __shared__ float hn[24][257];
    __shared__ float nrm[24];
    __shared__ float red[256];
    const int tid = threadIdx.x;
    const size_t rowbase = (size_t)blockIdx.x * 25 + 1;
    for (int idx = tid; idx < 24 * 256; idx += 256) {
        int i = idx >> 8, k = idx & 255;
        hn[i][k] = src[(rowbase + i) * 256 + k];
    }
    __syncthreads();
    if (tid < 24) {
        float s = 0.f;
        for (int k = 0; k < 256; k++) { float v = hn[tid][k]; s += v * v; }
        nrm[tid] = 1.f / (sqrtf(s) + 1e-8f);
    }
    __syncthreads();
    for (int idx = tid; idx < 24 * 256; idx += 256) {
        int i = idx >> 8, k = idx & 255;
        hn[i][k] *= nrm[i];
    }
    __syncthreads();
    float local = 0.f;
    for (int p = tid; p < 276; p += 256) {
        int i = 0, pp = p;
        while (pp >= 23 - i) { pp -= 23 - i; i++; }
        int j = i + 1 + pp;
        float d = 0.f;
#pragma unroll 8
        for (int k = 0; k < 256; k++) d += hn[i][k] * hn[j][k];
        local += fabsf(d);
    }
    red[tid] = local;
    __syncthreads();
    for (int s = 128; s > 0; s >>= 1) {
        if (tid < s) red[tid] += red[tid + s];
        __syncthreads();
    }
    if (tid == 0) g_red[out_base + blockIdx.x] = red[0] * (2.f / (24.f * 23.f));
}

__global__ void gol_finalize(float* __restrict__ out)
{
    __shared__ double red[256];
    int tid = threadIdx.x;
    double s1 = 0.0, s2 = 0.0;
    for (int i = tid; i < CSTEPS * CB; i += 256) s1 += (double)g_red[i];
    for (int i = tid; i < CB; i += 256) s2 += (double)g_red[CSTEPS * CB + i];
    red[tid] = s1 / (double)(CSTEPS * CB) + s2 / (double)CB;
    __syncthreads();
    for (int s = 128; s > 0; s >>= 1) {
        if (tid < s) red[tid] += red[tid + s];
        __syncthreads();
    }
    if (tid == 0) out[0] = (float)red[0];
}

// ---------------------------------------------------------------------------
extern "C" void kernel_launch(void* const* d_in, const int* in_sizes, int n_in,
                              void* d_out, int out_size)
{
    (void)in_sizes; (void)n_in; (void)out_size;
    const float* emb  = (const float*)d_in[0];
    const float* Wmsg = (const float*)d_in[1];
    const float* Wih  = (const float*)d_in[2];
    const float* Whh  = (const float*)d_in[3];
    const float* Wout = (const float*)d_in[4];
    const int*   perm = (const int*)d_in[5];

    float* out = (float*)d_out;
    float* o_gol  = out;
    float* o_lstm = out + 1;
    float* o_in   = out + 1 + (size_t)CNH;
    float* o_out  = out + 1 + 2 * (size_t)CNH;
    float* o_hs   = out + 1 + 3 * (size_t)CNH;

    float *px, *ph, *pgx, *pm, *pt2, *pgates, *poe;
    cudaGetSymbolAddress((void**)&px,     g_x);
    cudaGetSymbolAddress((void**)&ph,     g_h);
    cudaGetSymbolAddress((void**)&pgx,    g_gx);
    cudaGetSymbolAddress((void**)&pm,     g_m);
    cudaGetSymbolAddress((void**)&pt2,    g_t2);
    cudaGetSymbolAddress((void**)&pgates, g_gates);
    cudaGetSymbolAddress((void**)&poe,    g_oe);

    prep_kernel<<<128, 256>>>(Wmsg);
    gather_init<<<CNH / 256, 256>>>(emb, perm, o_lstm);

    // gx = x @ W_ih[:, :256]^T  — chain prefix of t1, reused every step
    sgemm_nt<<<dim3(8, CN / 128), 256>>>(256, px, 256, Wih, 512,
                                         pgx, 1024, nullptr, nullptr);

    for (int s = 0; s < CSTEPS; s++) {
        // fused: t2 = h @ W_hh^T  AND  A = h @ W1^T  (both depend only on h)
        step_pre<<<1000, 256>>>(Whh, Wmsg);
        // per-edge exact msg chains (paired-k, 2 dsts per block)
        msg_exact<<<dim3(12, CB), 128>>>();
        // gates = chain(gx -> m terms) + t2   (post-add, commutative)
        sgemm_nt<<<dim3(8, CN / 128), 256>>>(256, pm, 256, Wih + 256, 512,
                                             pgates, 1024, pgx, pt2);
        lstm_step<<<CNH / 1024, 256>>>(o_hs + (size_t)s * CNH);
    }

    // output_embeddings = h_last @ W_out^T
    sgemm_nt<<<dim3(2, CN / 128), 256>>>(256, ph, 256, Wout, 256,
                                         poe, 256, nullptr, nullptr);
    finalize_emb<<<CNH / 256, 256>>>(o_in, o_out);

    gol_kernel<<<CSTEPS * CB, 256>>>(o_hs, 0);
    gol_kernel<<<CB, 256>>>(poe, CSTEPS * CB);
    gol_finalize<<<1, 256>>>(o_gol);
}

// round 16
// speedup vs baseline: 1.0164x; 1.0164x over previous
#include <cuda_runtime.h>
#include <math.h>

// Problem constants
constexpr int CB = 512;        // batch
constexpr int CK = 25;         // nodes per board (incl. anchor node 0)
constexpr int CH = 256;        // hidden
constexpr int CSTEPS = 32;
constexpr int CN = CB * CK;    // 12800 nodes
constexpr int CNH = CN * CH;   // 3276800
constexpr int NPERS = 296;     // persistent GEMM grid (2 blocks x 148 SMs)

// Scratch (device globals; no allocation allowed)
__device__ float g_x[CNH];             // lstm_emb (constant x)
__device__ float g_h[CNH];             // hidden state
__device__ float g_c[CNH];             // cell state
__device__ float g_gx[CN * 1024];      // chain prefix: x @ W_ih[:, :256].T
__device__ float g_A[CNH];             // per-step A = h @ W1^T
__device__ float g_m[CNH];             // per-step messages
__device__ float g_t2[CN * 1024];      // per-step t2 = h @ W_hh^T
__device__ float g_gates[CN * 1024];   // gates
__device__ float g_W2P[256 * 256];     // W2 pair-packed
__device__ float g_oe[CNH];            // output_embeddings
__device__ float g_red[CSTEPS * CB + CB];  // per-block gol partials
__device__ unsigned int g_ctr[2 * CSTEPS + 2];  // per-launch tile counters

// ---------------------------------------------------------------------------
// Packed f32x2 helpers (Blackwell FFMA2) — bitwise identical per lane to scalar.
typedef unsigned long long u64;
__device__ __forceinline__ u64 pk2(float lo, float hi)
{
    u64 r; asm("mov.b64 %0, {%1, %2};" : "=l"(r) : "f"(lo), "f"(hi)); return r;
}
__device__ __forceinline__ float2 up2(u64 v)
{
    float2 f; asm("mov.b64 {%0, %1}, %2;" : "=f"(f.x), "=f"(f.y) : "l"(v)); return f;
}
__device__ __forceinline__ u64 ffma2(u64 a, u64 b, u64 c)
{
    u64 d; asm("fma.rn.f32x2 %0, %1, %2, %3;" : "=l"(d) : "l"(a), "l"(b), "l"(c));
    return d;
}

// ---------------------------------------------------------------------------
// XLA elementwise replicas (EmitFastTanh; logistic = 0.5 + 0.5*tanh(0.5x)).
__device__ __forceinline__ float xla_tanh(float x)
{
    float xc = fminf(fmaxf(x, -9.f), 9.f);
    float x2 = __fmul_rn(xc, xc);
    float np = fmaf(x2, -2.76076847742355e-16f, 2.00018790482477e-13f);
    np = fmaf(x2, np, -8.60467152213735e-11f);
    np = fmaf(x2, np,  5.12229709037114e-08f);
    np = fmaf(x2, np,  1.48572235717979e-05f);
    np = fmaf(x2, np,  6.37261928875436e-04f);
    np = fmaf(x2, np,  4.89352455891786e-03f);
    float num = __fmul_rn(xc, np);
    float dp = fmaf(x2, 1.19825839466702e-06f, 1.18534705686654e-04f);
    dp = fmaf(x2, dp, 2.26843463243900e-03f);
    dp = fmaf(x2, dp, 4.89352518554385e-03f);
    float r = __fdiv_rn(num, dp);
    return (fabsf(x) < 0.0004f) ? x : r;
}
__device__ __forceinline__ float xla_sigmoid(float x)
{
    return __fadd_rn(0.5f, __fmul_rn(0.5f, xla_tanh(__fmul_rn(0.5f, x))));
}

// ---------------------------------------------------------------------------
// W2 pair-packed layout + counter reset (runs every launch -> deterministic).
__global__ void prep_kernel(const float* __restrict__ Wmsg)
{
    int t = blockIdx.x * blockDim.x + threadIdx.x;
    if (t < 2 * CSTEPS + 2) g_ctr[t] = 0u;
    if (t >= 256 * 128) return;
    int k = t >> 7, rh = t & 127;
    size_t off = ((size_t)(k >> 1) * 128 + rh) * 4 + (k & 1) * 2;
    g_W2P[off]     = Wmsg[(2 * rh)     * 512 + 256 + k];
    g_W2P[off + 1] = Wmsg[(2 * rh + 1) * 512 + 256 + k];
}

// ---------------------------------------------------------------------------
__global__ void gather_init(const float* __restrict__ emb,
                            const int* __restrict__ perm,
                            float* __restrict__ out_lstm_emb)
{
    int gid = blockIdx.x * blockDim.x + threadIdx.x;
    if (gid >= CNH) return;
    int n = gid >> 8, h = gid & 255;
    float v = emb[(size_t)perm[n] * CH + h];
    g_x[gid] = v;
    out_lstm_emb[gid] = v;
    g_h[gid] = v;
    g_c[gid] = v;
    if (n % CK == 0) g_m[gid] = 0.f;   // node 0 never receives messages
}

// ---------------------------------------------------------------------------
// 256-thread GEMM tile (128x128 @ (by,bx)) of A[M,K] @ B[N,K]^T.
// One sequential fma chain over ascending k per output; FFMA2 lanes bitwise
// == scalar. M-paired accumulators; register double-buffered smem pipeline.
// Cinit != null : acc starts at Cinit (chain prefix).
// Cadd  != null : post-add (commutative).
__device__ __forceinline__ void sgemm_tile(
    int K,
    const float* __restrict__ A, int lda,
    const float* __restrict__ Bm, int ldb,
    float* __restrict__ C, int ldc,
    const float* __restrict__ Cinit,
    const float* __restrict__ Cadd,
    int bx, int by,
    float As[2][16][128], float Bs[2][16][128])
{
    const int tid = threadIdx.x;
    const int tx = tid & 15;
    const int ty = tid >> 4;
    const float* Ab = A + (size_t)by * 128 * lda;
    const float* Bb = Bm + (size_t)bx * 128 * ldb;
    const int lrow = tid >> 1;
    const int lk4b = (tid & 1) * 2;

    u64 acc2[4][8];   // [m-pair][j]; lanes = (row m0, row m1)
    if (Cinit) {
#pragma unroll
        for (int mp = 0; mp < 4; mp++) {
            int lr0 = (mp < 2) ? (ty * 4 + mp * 2) : (64 + ty * 4 + (mp - 2) * 2);
            size_t r0 = (size_t)by * 128 + lr0;
            const float* I0 = Cinit + r0 * ldc + (size_t)bx * 128;
            const float* I1 = I0 + ldc;
            float4 a0 = *(const float4*)(I0 + tx * 4);
            float4 a1 = *(const float4*)(I0 + 64 + tx * 4);
            float4 b0 = *(const float4*)(I1 + tx * 4);
            float4 b1 = *(const float4*)(I1 + 64 + tx * 4);
            acc2[mp][0] = pk2(a0.x, b0.x); acc2[mp][1] = pk2(a0.y, b0.y);
            acc2[mp][2] = pk2(a0.z, b0.z); acc2[mp][3] = pk2(a0.w, b0.w);
            acc2[mp][4] = pk2(a1.x, b1.x); acc2[mp][5] = pk2(a1.y, b1.y);
            acc2[mp][6] = pk2(a1.z, b1.z); acc2[mp][7] = pk2(a1.w, b1.w);
        }
    } else {
#pragma unroll
        for (int mp = 0; mp < 4; mp++)
#pragma unroll
            for (int j = 0; j < 8; j++) acc2[mp][j] = 0ull;
    }

    float4 avs[2], bvs[2];
#pragma unroll
    for (int u = 0; u < 2; u++) {
        int k4 = lk4b + u;
        avs[u] = *(const float4*)(Ab + (size_t)lrow * lda + k4 * 4);
        bvs[u] = *(const float4*)(Bb + (size_t)lrow * ldb + k4 * 4);
    }
#pragma unroll
    for (int u = 0; u < 2; u++) {
        int k4 = lk4b + u;
        As[0][k4 * 4 + 0][lrow] = avs[u].x;
        As[0][k4 * 4 + 1][lrow] = avs[u].y;
        As[0][k4 * 4 + 2][lrow] = avs[u].z;
        As[0][k4 * 4 + 3][lrow] = avs[u].w;
        Bs[0][k4 * 4 + 0][lrow] = bvs[u].x;
        Bs[0][k4 * 4 + 1][lrow] = bvs[u].y;
        Bs[0][k4 * 4 + 2][lrow] = bvs[u].z;
        Bs[0][k4 * 4 + 3][lrow] = bvs[u].w;
    }
    __syncthreads();

    const int T = K >> 4;
    int buf = 0;
    for (int t = 0; t < T; t++) {
        if (t + 1 < T) {
            int kt = (t + 1) * 16;
#pragma unroll
            for (int u = 0; u < 2; u++) {
                int k4 = lk4b + u;
                avs[u] = *(const float4*)(Ab + (size_t)lrow * lda + kt + k4 * 4);
                bvs[u] = *(const float4*)(Bb + (size_t)lrow * ldb + kt + k4 * 4);
            }
        }
#pragma unroll
        for (int k = 0; k < 16; k++) {
            u64 ap[4];
            ap[0] = *(const u64*)(&As[buf][k][ty * 4]);
            ap[1] = *(const u64*)(&As[buf][k][ty * 4 + 2]);
            ap[2] = *(const u64*)(&As[buf][k][64 + ty * 4]);
            ap[3] = *(const u64*)(&As[buf][k][64 + ty * 4 + 2]);
            float b[8];
            *(float4*)(b)     = *(const float4*)(&Bs[buf][k][tx * 4]);
            *(float4*)(b + 4) = *(const float4*)(&Bs[buf][k][64 + tx * 4]);
#pragma unroll
            for (int j = 0; j < 8; j++) {
                u64 bd = pk2(b[j], b[j]);
#pragma unroll
                for (int mp = 0; mp < 4; mp++)
                    acc2[mp][j] = ffma2(ap[mp], bd, acc2[mp][j]);
            }
        }
        if (t + 1 < T) {
            int nb = buf ^ 1;
#pragma unroll
            for (int u = 0; u < 2; u++) {
                int k4 = lk4b + u;
                As[nb][k4 * 4 + 0][lrow] = avs[u].x;
                As[nb][k4 * 4 + 1][lrow] = avs[u].y;
                As[nb][k4 * 4 + 2][lrow] = avs[u].z;
                As[nb][k4 * 4 + 3][lrow] = avs[u].w;
                Bs[nb][k4 * 4 + 0][lrow] = bvs[u].x;
                Bs[nb][k4 * 4 + 1][lrow] = bvs[u].y;
                Bs[nb][k4 * 4 + 2][lrow] = bvs[u].z;
                Bs[nb][k4 * 4 + 3][lrow] = bvs[u].w;
            }
            __syncthreads();
            buf = nb;
        }
    }

#pragma unroll
    for (int mp = 0; mp < 4; mp++) {
        int lr0 = (mp < 2) ? (ty * 4 + mp * 2) : (64 + ty * 4 + (mp - 2) * 2);
        size_t r0 = (size_t)by * 128 + lr0;
        float* C0 = C + r0 * ldc + (size_t)bx * 128;
        float* C1 = C0 + ldc;
        float2 p[8];
#pragma unroll
        for (int j = 0; j < 8; j++) p[j] = up2(acc2[mp][j]);
        float4 v00 = make_float4(p[0].x, p[1].x, p[2].x, p[3].x);
        float4 v01 = make_float4(p[4].x, p[5].x, p[6].x, p[7].x);
        float4 v10 = make_float4(p[0].y, p[1].y, p[2].y, p[3].y);
        float4 v11 = make_float4(p[4].y, p[5].y, p[6].y, p[7].y);
        if (Cadd) {
            const float* A0 = Cadd + r0 * ldc + (size_t)bx * 128;
            const float* A1 = A0 + ldc;
            float4 c00 = *(const float4*)(A0 + tx * 4);
            float4 c01 = *(const float4*)(A0 + 64 + tx * 4);
            float4 c10 = *(const float4*)(A1 + tx * 4);
            float4 c11 = *(const float4*)(A1 + 64 + tx * 4);
            v00.x = __fadd_rn(v00.x, c00.x); v00.y = __fadd_rn(v00.y, c00.y);
            v00.z = __fadd_rn(v00.z, c00.z); v00.w = __fadd_rn(v00.w, c00.w);
            v01.x = __fadd_rn(v01.x, c01.x); v01.y = __fadd_rn(v01.y, c01.y);
            v01.z = __fadd_rn(v01.z, c01.z); v01.w = __fadd_rn(v01.w, c01.w);
            v10.x = __fadd_rn(v10.x, c10.x); v10.y = __fadd_rn(v10.y, c10.y);
            v10.z = __fadd_rn(v10.z, c10.z); v10.w = __fadd_rn(v10.w, c10.w);
            v11.x = __fadd_rn(v11.x, c11.x); v11.y = __fadd_rn(v11.y, c11.y);
            v11.z = __fadd_rn(v11.z, c11.z); v11.w = __fadd_rn(v11.w, c11.w);
        }
        *(float4*)(C0 + tx * 4) = v00;
        *(float4*)(C0 + 64 + tx * 4) = v01;
        *(float4*)(C1 + tx * 4) = v10;
        *(float4*)(C1 + 64 + tx * 4) = v11;
    }
}

__global__ __launch_bounds__(256, 2) void sgemm_nt(
    int K,
    const float* __restrict__ A, int lda,
    const float* __restrict__ Bm, int ldb,
    float* __restrict__ C, int ldc,
    const float* __restrict__ Cinit,
    const float* __restrict__ Cadd)
{
    __shared__ float As[2][16][128];
    __shared__ float Bs[2][16][128];
    sgemm_tile(K, A, lda, Bm, ldb, C, ldc, Cinit, Cadd,
               blockIdx.x, blockIdx.y, As, Bs);
}

// ---------------------------------------------------------------------------
// Persistent step_pre: 296 blocks dynamically pull 1000 tiles
// (0..799: t2 = h @ W_hh^T ; 800..999: A = h @ W1^T).
// Tile->block assignment affects scheduling only; each tile's arithmetic and
// output location are fixed -> bitwise identical results.
__global__ __launch_bounds__(256, 2) void step_pre_p(
    const float* __restrict__ Whh, const float* __restrict__ Wmsg, int slot)
{
    __shared__ float As[2][16][128];
    __shared__ float Bs[2][16][128];
    __shared__ int s_tile;
    for (;;) {
        if (threadIdx.x == 0) s_tile = (int)atomicAdd(&g_ctr[slot], 1u);
        __syncthreads();
        int bid = s_tile;
        if (bid >= 1000) return;
        if (bid < 800) {
            sgemm_tile(256, g_h, 256, Whh, 256, g_t2, 1024, nullptr, nullptr,
                       bid & 7, bid >> 3, As, Bs);
        } else {
            int i = bid - 800;
            sgemm_tile(256, g_h, 256, Wmsg, 512, g_A, 256, nullptr, nullptr,
                       i & 1, i >> 1, As, Bs);
        }
        __syncthreads();
    }
}

// Persistent gates GEMM: 296 blocks pull 800 tiles.
__global__ __launch_bounds__(256, 2) void gates_p(
    const float* __restrict__ Wih, int slot)
{
    __shared__ float As[2][16][128];
    __shared__ float Bs[2][16][128];
    __shared__ int s_tile;
    for (;;) {
        if (threadIdx.x == 0) s_tile = (int)atomicAdd(&g_ctr[slot], 1u);
        __syncthreads();
        int bid = s_tile;
        if (bid >= 800) return;
        sgemm_tile(256, g_m, 256, Wih + 256, 512, g_gates, 1024, g_gx, g_t2,
                   bid & 7, bid >> 3, As, Bs);
        __syncthreads();
    }
}

// ---------------------------------------------------------------------------
// Exact per-edge msg chains, FFMA2, paired-k inner loop (round-14 version):
// one LDG.128 + one LDS.128 per 2 k's; chain per output r: acc = A_i[r],
// ascending k, ascending-i sum with i != j — bitwise identical to scalar.
__global__ __launch_bounds__(128) void msg_exact()
{
    __shared__ u64 hj2[256];               // duplicated lanes: (h[k], h[k])
    const int j = blockIdx.x;
    const int b = blockIdx.y;
    const int base = b * CK + 1;
    const int rh = threadIdx.x;

    {
        float v0 = g_h[(size_t)(base + j) * CH + rh];
        float v1 = g_h[(size_t)(base + j) * CH + rh + 128];
        hj2[rh] = pk2(v0, v0);
        hj2[rh + 128] = pk2(v1, v1);
    }
    __syncthreads();

    u64 acc[24];
#pragma unroll
    for (int i = 0; i < 24; i++)
        acc[i] = *(const u64*)(&g_A[(size_t)(base + i) * CH + 2 * rh]);

    const ulonglong2* wp = (const ulonglong2*)g_W2P + rh;
#pragma unroll 2
    for (int kp = 0; kp < 128; kp++) {
        ulonglong2 w = wp[(size_t)kp * 128];
        ulonglong2 h = *(const ulonglong2*)(&hj2[2 * kp]);
#pragma unroll
        for (int i = 0; i < 24; i++) {
            acc[i] = ffma2(h.x, w.x, acc[i]);   // k = 2kp
            acc[i] = ffma2(h.y, w.y, acc[i]);   // k = 2kp+1
        }
    }

    float mlo = 0.f, mhi = 0.f;
#pragma unroll
    for (int i = 0; i < 24; i++)
        if (i != j) {
            float2 e = up2(acc[i]);
            mlo = __fadd_rn(mlo, fmaxf(e.x, 0.f));
            mhi = __fadd_rn(mhi, fmaxf(e.y, 0.f));
        }
    *(float2*)(&g_m[(size_t)(base + j) * CH + 2 * rh]) = make_float2(mlo, mhi);
}

// ---------------------------------------------------------------------------
// LSTM pointwise, float4-vectorized on internal buffers; scalar stores to the
// (4B-aligned) output slice.
__global__ void lstm_step(float* __restrict__ hs_slice)
{
    int t = blockIdx.x * blockDim.x + threadIdx.x;
    if (t >= CNH / 4) return;
    int n = t >> 6;
    int h4 = t & 63;
    const float4* g = (const float4*)(g_gates + (size_t)n * 1024);
    float4 ig = g[h4], fg = g[64 + h4], gg = g[128 + h4], og = g[192 + h4];
    float4 c = *(const float4*)(g_c + (size_t)t * 4);
    float4 nc, nh;
    {
        float si = xla_sigmoid(ig.x), sf = xla_sigmoid(fg.x), so = xla_sigmoid(og.x);
        nc.x = __fadd_rn(__fmul_rn(sf, c.x), __fmul_rn(si, xla_tanh(gg.x)));
        nh.x = __fmul_rn(so, xla_tanh(nc.x));
    }
    {
        float si = xla_sigmoid(ig.y), sf = xla_sigmoid(fg.y), so = xla_sigmoid(og.y);
        nc.y = __fadd_rn(__fmul_rn(sf, c.y), __fmul_rn(si, xla_tanh(gg.y)));
        nh.y = __fmul_rn(so, xla_tanh(nc.y));
    }
    {
        float si = xla_sigmoid(ig.z), sf = xla_sigmoid(fg.z), so = xla_sigmoid(og.z);
        nc.z = __fadd_rn(__fmul_rn(sf, c.z), __fmul_rn(si, xla_tanh(gg.z)));
        nh.z = __fmul_rn(so, xla_tanh(nc.z));
    }
    {
        float si = xla_sigmoid(ig.w), sf = xla_sigmoid(fg.w), so = xla_sigmoid(og.w);
        nc.w = __fadd_rn(__fmul_rn(sf, c.w), __fmul_rn(si, xla_tanh(gg.w)));
        nh.w = __fmul_rn(so, xla_tanh(nc.w));
    }
    *(float4*)(g_c + (size_t)t * 4) = nc;
    *(float4*)(g_h + (size_t)t * 4) = nh;
    float* hp = hs_slice + (size_t)t * 4;
    hp[0] = nh.x; hp[1] = nh.y; hp[2] = nh.z; hp[3] = nh.w;
}

// ---------------------------------------------------------------------------
__global__ void finalize_emb(float* __restrict__ o_in, float* __restrict__ o_out)
{
    int gid = blockIdx.x * blockDim.x + threadIdx.x;
    if (gid >= CNH) return;
    int n = gid >> 8;
    bool anchor = (n % CK) == 0;
    float xv = g_x[gid];
    float hv = g_h[gid];
    float ov = g_oe[gid];
    o_in[gid]  = anchor ? xv : hv;
    o_out[gid] = anchor ? xv : ov;
}

// ---------------------------------------------------------------------------
__global__ __launch_bounds__(256) void gol_kernel(const float* __restrict__ src, int out_base)
{
    __shared__ float hn[24][257];
    __shared__ float nrm[24];
    __shared__ float red[256];
    const int tid = threadIdx.x;
    const size_t rowbase = (size_t)blockIdx.x * 25 + 1;
    for (int idx = tid; idx < 24 * 256; idx += 256) {
        int i = idx >> 8, k = idx & 255;
        hn[i][k] = src[(rowbase + i) * 256 + k];
    }
    __syncthreads();
    if (tid < 24) {
        float s = 0.f;
        for (int k = 0; k < 256; k++) { float v = hn[tid][k]; s += v * v; }
        nrm[tid] = 1.f / (sqrtf(s) + 1e-8f);
    }
    __syncthreads();
    for (int idx = tid; idx < 24 * 256; idx += 256) {
        int i = idx >> 8, k = idx & 255;
        hn[i][k] *= nrm[i];
    }
    __syncthreads();
    float local = 0.f;
    for (int p = tid; p < 276; p += 256) {
        int i = 0, pp = p;
        while (pp >= 23 - i) { pp -= 23 - i; i++; }
        int j = i + 1 + pp;
        float d = 0.f;
#pragma unroll 8
        for (int k = 0; k < 256; k++) d += hn[i][k] * hn[j][k];
        local += fabsf(d);
    }
    red[tid] = local;
    __syncthreads();
    for (int s = 128; s > 0; s >>= 1) {
        if (tid < s) red[tid] += red[tid + s];
        __syncthreads();
    }
    if (tid == 0) g_red[out_base + blockIdx.x] = red[0] * (2.f / (24.f * 23.f));
}

__global__ void gol_finalize(float* __restrict__ out)
{
    __shared__ double red[256];
    int tid = threadIdx.x;
    double s1 = 0.0, s2 = 0.0;
    for (int i = tid; i < CSTEPS * CB; i += 256) s1 += (double)g_red[i];
    for (int i = tid; i < CB; i += 256) s2 += (double)g_red[CSTEPS * CB + i];
    red[tid] = s1 / (double)(CSTEPS * CB) + s2 / (double)CB;
    __syncthreads();
    for (int s = 128; s > 0; s >>= 1) {
        if (tid < s) red[tid] += red[tid + s];
        __syncthreads();
    }
    if (tid == 0) out[0] = (float)red[0];
}

// ---------------------------------------------------------------------------
extern "C" void kernel_launch(void* const* d_in, const int* in_sizes, int n_in,
                              void* d_out, int out_size)
{
    (void)in_sizes; (void)n_in; (void)out_size;
    const float* emb  = (const float*)d_in[0];
    const float* Wmsg = (const float*)d_in[1];
    const float* Wih  = (const float*)d_in[2];
    const float* Whh  = (const float*)d_in[3];
    const float* Wout = (const float*)d_in[4];
    const int*   perm = (const int*)d_in[5];

    float* out = (float*)d_out;
    float* o_gol  = out;
    float* o_lstm = out + 1;
    float* o_in   = out + 1 + (size_t)CNH;
    float* o_out  = out + 1 + 2 * (size_t)CNH;
    float* o_hs   = out + 1 + 3 * (size_t)CNH;

    float *px, *ph, *pgx, *poe;
    cudaGetSymbolAddress((void**)&px,  g_x);
    cudaGetSymbolAddress((void**)&ph,  g_h);
    cudaGetSymbolAddress((void**)&pgx, g_gx);
    cudaGetSymbolAddress((void**)&poe, g_oe);

    prep_kernel<<<128, 256>>>(Wmsg);
    gather_init<<<CNH / 256, 256>>>(emb, perm, o_lstm);

    // gx = x @ W_ih[:, :256]^T  — chain prefix of t1, reused every step
    sgemm_nt<<<dim3(8, CN / 128), 256>>>(256, px, 256, Wih, 512,
                                         pgx, 1024, nullptr, nullptr);

    for (int s = 0; s < CSTEPS; s++) {
        // persistent fused pre-GEMMs: t2 AND A (dynamic tile pull, no wave tail)
        step_pre_p<<<NPERS, 256>>>(Whh, Wmsg, 2 * s);
        // per-edge exact msg chains (paired-k)
        msg_exact<<<dim3(24, CB), 128>>>();
        // persistent gates GEMM: chain(gx -> m terms) + t2
        gates_p<<<NPERS, 256>>>(Wih, 2 * s + 1);
        lstm_step<<<CNH / 1024, 256>>>(o_hs + (size_t)s * CNH);
    }

    // output_embeddings = h_last @ W_out^T
    sgemm_nt<<<dim3(2, CN / 128), 256>>>(256, ph, 256, Wout, 256,
                                         poe, 256, nullptr, nullptr);
    finalize_emb<<<CNH / 256, 256>>>(o_in, o_out);

    gol_kernel<<<CSTEPS * CB, 256>>>(o_hs, 0);
    gol_kernel<<<CB, 256>>>(poe, CSTEPS * CB);
    gol_finalize<<<1, 256>>>(o_gol);
}

// round 17
// speedup vs baseline: 1.0294x; 1.0128x over previous
#include <cuda_runtime.h>
#include <math.h>

// Problem constants
constexpr int CB = 512;        // batch
constexpr int CK = 25;         // nodes per board (incl. anchor node 0)
constexpr int CH = 256;        // hidden
constexpr int CSTEPS = 32;
constexpr int CN = CB * CK;    // 12800 nodes
constexpr int CNH = CN * CH;   // 3276800

// Scratch (device globals; no allocation allowed)
__device__ float g_x[CNH];             // lstm_emb (constant x)
__device__ float g_h[CNH];             // hidden state
__device__ float g_c[CNH];             // cell state
__device__ float g_gx[CN * 1024];      // chain prefix: x @ W_ih[:, :256].T
__device__ float g_A[CNH];             // per-step A = h @ W1^T
__device__ float g_m[CNH];             // per-step messages
__device__ float g_t2[CN * 1024];      // per-step t2 = h @ W_hh^T
__device__ float g_gates[CN * 1024];   // gates
__device__ float g_W2P[256 * 256];     // W2 pair-packed: (k-pair, rh) -> 2x u64 lanes
__device__ float g_oe[CNH];            // output_embeddings
__device__ float g_red[CSTEPS * CB + CB];  // per-block gol partials

// ---------------------------------------------------------------------------
// Packed f32x2 helpers (Blackwell FFMA2) — bitwise identical per lane to scalar.
typedef unsigned long long u64;
__device__ __forceinline__ u64 pk2(float lo, float hi)
{
    u64 r; asm("mov.b64 %0, {%1, %2};" : "=l"(r) : "f"(lo), "f"(hi)); return r;
}
__device__ __forceinline__ float2 up2(u64 v)
{
    float2 f; asm("mov.b64 {%0, %1}, %2;" : "=f"(f.x), "=f"(f.y) : "l"(v)); return f;
}
__device__ __forceinline__ u64 ffma2(u64 a, u64 b, u64 c)
{
    u64 d; asm("fma.rn.f32x2 %0, %1, %2, %3;" : "=l"(d) : "l"(a), "l"(b), "l"(c));
    return d;
}

// ---------------------------------------------------------------------------
// XLA elementwise replicas (EmitFastTanh; logistic = 0.5 + 0.5*tanh(0.5x)).
__device__ __forceinline__ float xla_tanh(float x)
{
    float xc = fminf(fmaxf(x, -9.f), 9.f);
    float x2 = __fmul_rn(xc, xc);
    float np = fmaf(x2, -2.76076847742355e-16f, 2.00018790482477e-13f);
    np = fmaf(x2, np, -8.60467152213735e-11f);
    np = fmaf(x2, np,  5.12229709037114e-08f);
    np = fmaf(x2, np,  1.48572235717979e-05f);
    np = fmaf(x2, np,  6.37261928875436e-04f);
    np = fmaf(x2, np,  4.89352455891786e-03f);
    float num = __fmul_rn(xc, np);
    float dp = fmaf(x2, 1.19825839466702e-06f, 1.18534705686654e-04f);
    dp = fmaf(x2, dp, 2.26843463243900e-03f);
    dp = fmaf(x2, dp, 4.89352518554385e-03f);
    float r = __fdiv_rn(num, dp);
    return (fabsf(x) < 0.0004f) ? x : r;
}
__device__ __forceinline__ float xla_sigmoid(float x)
{
    return __fadd_rn(0.5f, __fmul_rn(0.5f, xla_tanh(__fmul_rn(0.5f, x))));
}

// ---------------------------------------------------------------------------
// W2 pair-packed layout for one-LDG.128-per-2k in msg_exact:
//   float offset of (k, rh, lane) = ((k>>1)*128 + rh)*4 + (k&1)*2 + lane
//   lane 0 -> output r=2rh, lane 1 -> r=2rh+1;  W2[r][k] = Wmsg[r*512+256+k]
__global__ void prep_kernel(const float* __restrict__ Wmsg)
{
    int t = blockIdx.x * blockDim.x + threadIdx.x;
    if (t >= 256 * 128) return;
    int k = t >> 7, rh = t & 127;
    size_t off = ((size_t)(k >> 1) * 128 + rh) * 4 + (k & 1) * 2;
    g_W2P[off]     = Wmsg[(2 * rh)     * 512 + 256 + k];
    g_W2P[off + 1] = Wmsg[(2 * rh + 1) * 512 + 256 + k];
}

// ---------------------------------------------------------------------------
__global__ void gather_init(const float* __restrict__ emb,
                            const int* __restrict__ perm,
                            float* __restrict__ out_lstm_emb)
{
    int gid = blockIdx.x * blockDim.x + threadIdx.x;
    if (gid >= CNH) return;
    int n = gid >> 8, h = gid & 255;
    float v = emb[(size_t)perm[n] * CH + h];
    g_x[gid] = v;
    out_lstm_emb[gid] = v;
    g_h[gid] = v;
    g_c[gid] = v;
    if (n % CK == 0) g_m[gid] = 0.f;   // node 0 never receives messages
}

// ---------------------------------------------------------------------------
// 256-thread GEMM tile (128x128 @ (by,bx)) of A[M,K] @ B[N,K]^T.
// One sequential fma chain over ascending k per output; FFMA2 lanes bitwise
// == scalar. M-paired accumulators; register double-buffered smem pipeline.
// Cinit != null : acc starts at Cinit (chain prefix).
// Cadd  != null : post-add (commutative).
__device__ __forceinline__ void sgemm_tile(
    int K,
    const float* __restrict__ A, int lda,
    const float* __restrict__ Bm, int ldb,
    float* __restrict__ C, int ldc,
    const float* __restrict__ Cinit,
    const float* __restrict__ Cadd,
    int bx, int by,
    float As[2][16][128], float Bs[2][16][128])
{
    const int tid = threadIdx.x;
    const int tx = tid & 15;
    const int ty = tid >> 4;
    const float* Ab = A + (size_t)by * 128 * lda;
    const float* Bb = Bm + (size_t)bx * 128 * ldb;
    const int lrow = tid >> 1;
    const int lk4b = (tid & 1) * 2;

    u64 acc2[4][8];   // [m-pair][j]; lanes = (row m0, row m1)
    if (Cinit) {
#pragma unroll
        for (int mp = 0; mp < 4; mp++) {
            int lr0 = (mp < 2) ? (ty * 4 + mp * 2) : (64 + ty * 4 + (mp - 2) * 2);
            size_t r0 = (size_t)by * 128 + lr0;
            const float* I0 = Cinit + r0 * ldc + (size_t)bx * 128;
            const float* I1 = I0 + ldc;
            float4 a0 = *(const float4*)(I0 + tx * 4);
            float4 a1 = *(const float4*)(I0 + 64 + tx * 4);
            float4 b0 = *(const float4*)(I1 + tx * 4);
            float4 b1 = *(const float4*)(I1 + 64 + tx * 4);
            acc2[mp][0] = pk2(a0.x, b0.x); acc2[mp][1] = pk2(a0.y, b0.y);
            acc2[mp][2] = pk2(a0.z, b0.z); acc2[mp][3] = pk2(a0.w, b0.w);
            acc2[mp][4] = pk2(a1.x, b1.x); acc2[mp][5] = pk2(a1.y, b1.y);
            acc2[mp][6] = pk2(a1.z, b1.z); acc2[mp][7] = pk2(a1.w, b1.w);
        }
    } else {
#pragma unroll
        for (int mp = 0; mp < 4; mp++)
#pragma unroll
            for (int j = 0; j < 8; j++) acc2[mp][j] = 0ull;
    }

    float4 avs[2], bvs[2];
#pragma unroll
    for (int u = 0; u < 2; u++) {
        int k4 = lk4b + u;
        avs[u] = *(const float4*)(Ab + (size_t)lrow * lda + k4 * 4);
        bvs[u] = *(const float4*)(Bb + (size_t)lrow * ldb + k4 * 4);
    }
#pragma unroll
    for (int u = 0; u < 2; u++) {
        int k4 = lk4b + u;
        As[0][k4 * 4 + 0][lrow] = avs[u].x;
        As[0][k4 * 4 + 1][lrow] = avs[u].y;
        As[0][k4 * 4 + 2][lrow] = avs[u].z;
        As[0][k4 * 4 + 3][lrow] = avs[u].w;
        Bs[0][k4 * 4 + 0][lrow] = bvs[u].x;
        Bs[0][k4 * 4 + 1][lrow] = bvs[u].y;
        Bs[0][k4 * 4 + 2][lrow] = bvs[u].z;
        Bs[0][k4 * 4 + 3][lrow] = bvs[u].w;
    }
    __syncthreads();

    const int T = K >> 4;
    int buf = 0;
    for (int t = 0; t < T; t++) {
        if (t + 1 < T) {
            int kt = (t + 1) * 16;
#pragma unroll
            for (int u = 0; u < 2; u++) {
                int k4 = lk4b + u;
                avs[u] = *(const float4*)(Ab + (size_t)lrow * lda + kt + k4 * 4);
                bvs[u] = *(const float4*)(Bb + (size_t)lrow * ldb + kt + k4 * 4);
            }
        }
#pragma unroll
        for (int k = 0; k < 16; k++) {
            u64 ap[4];
            ap[0] = *(const u64*)(&As[buf][k][ty * 4]);
            ap[1] = *(const u64*)(&As[buf][k][ty * 4 + 2]);
            ap[2] = *(const u64*)(&As[buf][k][64 + ty * 4]);
            ap[3] = *(const u64*)(&As[buf][k][64 + ty * 4 + 2]);
            float b[8];
            *(float4*)(b)     = *(const float4*)(&Bs[buf][k][tx * 4]);
            *(float4*)(b + 4) = *(const float4*)(&Bs[buf][k][64 + tx * 4]);
#pragma unroll
            for (int j = 0; j < 8; j++) {
                u64 bd = pk2(b[j], b[j]);
#pragma unroll
                for (int mp = 0; mp < 4; mp++)
                    acc2[mp][j] = ffma2(ap[mp], bd, acc2[mp][j]);
            }
        }
        if (t + 1 < T) {
            int nb = buf ^ 1;
#pragma unroll
            for (int u = 0; u < 2; u++) {
                int k4 = lk4b + u;
                As[nb][k4 * 4 + 0][lrow] = avs[u].x;
                As[nb][k4 * 4 + 1][lrow] = avs[u].y;
                As[nb][k4 * 4 + 2][lrow] = avs[u].z;
                As[nb][k4 * 4 + 3][lrow] = avs[u].w;
                Bs[nb][k4 * 4 + 0][lrow] = bvs[u].x;
                Bs[nb][k4 * 4 + 1][lrow] = bvs[u].y;
                Bs[nb][k4 * 4 + 2][lrow] = bvs[u].z;
                Bs[nb][k4 * 4 + 3][lrow] = bvs[u].w;
            }
            __syncthreads();
            buf = nb;
        }
    }

#pragma unroll
    for (int mp = 0; mp < 4; mp++) {
        int lr0 = (mp < 2) ? (ty * 4 + mp * 2) : (64 + ty * 4 + (mp - 2) * 2);
        size_t r0 = (size_t)by * 128 + lr0;
        float* C0 = C + r0 * ldc + (size_t)bx * 128;
        float* C1 = C0 + ldc;
        float2 p[8];
#pragma unroll
        for (int j = 0; j < 8; j++) p[j] = up2(acc2[mp][j]);
        float4 v00 = make_float4(p[0].x, p[1].x, p[2].x, p[3].x);
        float4 v01 = make_float4(p[4].x, p[5].x, p[6].x, p[7].x);
        float4 v10 = make_float4(p[0].y, p[1].y, p[2].y, p[3].y);
        float4 v11 = make_float4(p[4].y, p[5].y, p[6].y, p[7].y);
        if (Cadd) {
            const float* A0 = Cadd + r0 * ldc + (size_t)bx * 128;
            const float* A1 = A0 + ldc;
            float4 c00 = *(const float4*)(A0 + tx * 4);
            float4 c01 = *(const float4*)(A0 + 64 + tx * 4);
            float4 c10 = *(const float4*)(A1 + tx * 4);
            float4 c11 = *(const float4*)(A1 + 64 + tx * 4);
            v00.x = __fadd_rn(v00.x, c00.x); v00.y = __fadd_rn(v00.y, c00.y);
            v00.z = __fadd_rn(v00.z, c00.z); v00.w = __fadd_rn(v00.w, c00.w);
            v01.x = __fadd_rn(v01.x, c01.x); v01.y = __fadd_rn(v01.y, c01.y);
            v01.z = __fadd_rn(v01.z, c01.z); v01.w = __fadd_rn(v01.w, c01.w);
            v10.x = __fadd_rn(v10.x, c10.x); v10.y = __fadd_rn(v10.y, c10.y);
            v10.z = __fadd_rn(v10.z, c10.z); v10.w = __fadd_rn(v10.w, c10.w);
            v11.x = __fadd_rn(v11.x, c11.x); v11.y = __fadd_rn(v11.y, c11.y);
            v11.z = __fadd_rn(v11.z, c11.z); v11.w = __fadd_rn(v11.w, c11.w);
        }
        *(float4*)(C0 + tx * 4) = v00;
        *(float4*)(C0 + 64 + tx * 4) = v01;
        *(float4*)(C1 + tx * 4) = v10;
        *(float4*)(C1 + 64 + tx * 4) = v11;
    }
}

__global__ __launch_bounds__(256, 2) void sgemm_nt(
    int K,
    const float* __restrict__ A, int lda,
    const float* __restrict__ Bm, int ldb,
    float* __restrict__ C, int ldc,
    const float* __restrict__ Cinit,
    const float* __restrict__ Cadd)
{
    __shared__ float As[2][16][128];
    __shared__ float Bs[2][16][128];
    sgemm_tile(K, A, lda, Bm, ldb, C, ldc, Cinit, Cadd,
               blockIdx.x, blockIdx.y, As, Bs);
}

// Fused pre-msg launch: blocks 0..799 compute t2 = h @ W_hh^T,
// blocks 800..999 compute A = h @ W1^T. Both depend only on h.
__global__ __launch_bounds__(256, 2) void step_pre(
    const float* __restrict__ Whh, const float* __restrict__ Wmsg)
{
    __shared__ float As[2][16][128];
    __shared__ float Bs[2][16][128];
    int bid = blockIdx.x;
    if (bid < 800) {
        sgemm_tile(256, g_h, 256, Whh, 256, g_t2, 1024, nullptr, nullptr,
                   bid & 7, bid >> 3, As, Bs);
    } else {
        int i = bid - 800;
        sgemm_tile(256, g_h, 256, Wmsg, 512, g_A, 256, nullptr, nullptr,
                   i & 1, i >> 1, As, Bs);
    }
}

// ---------------------------------------------------------------------------
// Exact per-edge msg chains, FFMA2, paired-k inner loop, 23 chains only:
// the i == j chain was computed and then DISCARDED by the sum — skip it
// entirely (4.2% of all msg FFMA2s were pure waste). Index map
// i = t + (t >= j), t = 0..22, resolved once before the k-loop (j is
// block-uniform -> no divergence). Each surviving chain: acc = A_i[r],
// ascending k (k, k+1). Sum over ascending t == ascending i skipping j —
// exactly the order used before. Bitwise identical.
__global__ __launch_bounds__(128) void msg_exact()
{
    __shared__ u64 hj2[256];               // duplicated lanes: (h[k], h[k])
    const int j = blockIdx.x;
    const int b = blockIdx.y;
    const int base = b * CK + 1;
    const int rh = threadIdx.x;

    {
        float v0 = g_h[(size_t)(base + j) * CH + rh];
        float v1 = g_h[(size_t)(base + j) * CH + rh + 128];
        hj2[rh] = pk2(v0, v0);
        hj2[rh + 128] = pk2(v1, v1);
    }
    __syncthreads();

    u64 acc[23];
#pragma unroll
    for (int t = 0; t < 23; t++) {
        int i = t + (t >= j ? 1 : 0);
        acc[t] = *(const u64*)(&g_A[(size_t)(base + i) * CH + 2 * rh]);
    }

    // W2P: ulonglong2 index (kp*128 + rh) holds (w_k, w_{k+1}) for outputs
    // (2rh, 2rh+1)
    const ulonglong2* wp = (const ulonglong2*)g_W2P + rh;
#pragma unroll 2
    for (int kp = 0; kp < 128; kp++) {
        ulonglong2 w = wp[(size_t)kp * 128];
        ulonglong2 h = *(const ulonglong2*)(&hj2[2 * kp]);
#pragma unroll
        for (int t = 0; t < 23; t++) {
            acc[t] = ffma2(h.x, w.x, acc[t]);   // k = 2kp
            acc[t] = ffma2(h.y, w.y, acc[t]);   // k = 2kp+1
        }
    }

    float mlo = 0.f, mhi = 0.f;
#pragma unroll
    for (int t = 0; t < 23; t++) {
        float2 e = up2(acc[t]);
        mlo = __fadd_rn(mlo, fmaxf(e.x, 0.f));
        mhi = __fadd_rn(mhi, fmaxf(e.y, 0.f));
    }
    *(float2*)(&g_m[(size_t)(base + j) * CH + 2 * rh]) = make_float2(mlo, mhi);
}

// ---------------------------------------------------------------------------
// LSTM pointwise, float4-vectorized on internal buffers; scalar stores to the
// (4B-aligned) output slice.
__global__ void lstm_step(float* __restrict__ hs_slice)
{
    int t = blockIdx.x * blockDim.x + threadIdx.x;
    if (t >= CNH / 4) return;
    int n = t >> 6;
    int h4 = t & 63;
    const float4* g = (const float4*)(g_gates + (size_t)n * 1024);
    float4 ig = g[h4], fg = g[64 + h4], gg = g[128 + h4], og = g[192 + h4];
    float4 c = *(const float4*)(g_c + (size_t)t * 4);
    float4 nc, nh;
    {
        float si = xla_sigmoid(ig.x), sf = xla_sigmoid(fg.x), so = xla_sigmoid(og.x);
        nc.x = __fadd_rn(__fmul_rn(sf, c.x), __fmul_rn(si, xla_tanh(gg.x)));
        nh.x = __fmul_rn(so, xla_tanh(nc.x));
    }
    {
        float si = xla_sigmoid(ig.y), sf = xla_sigmoid(fg.y), so = xla_sigmoid(og.y);
        nc.y = __fadd_rn(__fmul_rn(sf, c.y), __fmul_rn(si, xla_tanh(gg.y)));
        nh.y = __fmul_rn(so, xla_tanh(nc.y));
    }
    {
        float si = xla_sigmoid(ig.z), sf = xla_sigmoid(fg.z), so = xla_sigmoid(og.z);
        nc.z = __fadd_rn(__fmul_rn(sf, c.z), __fmul_rn(si, xla_tanh(gg.z)));
        nh.z = __fmul_rn(so, xla_tanh(nc.z));
    }
    {
        float si = xla_sigmoid(ig.w), sf = xla_sigmoid(fg.w), so = xla_sigmoid(og.w);
        nc.w = __fadd_rn(__fmul_rn(sf, c.w), __fmul_rn(si, xla_tanh(gg.w)));
        nh.w = __fmul_rn(so, xla_tanh(nc.w));
    }
    *(float4*)(g_c + (size_t)t * 4) = nc;
    *(float4*)(g_h + (size_t)t * 4) = nh;
    float* hp = hs_slice + (size_t)t * 4;
    hp[0] = nh.x; hp[1] = nh.y; hp[2] = nh.z; hp[3] = nh.w;
}

// ---------------------------------------------------------------------------
__global__ void finalize_emb(float* __restrict__ o_in, float* __restrict__ o_out)
{
    int gid = blockIdx.x * blockDim.x + threadIdx.x;
    if (gid >= CNH) return;
    int n = gid >> 8;
    bool anchor = (n % CK) == 0;
    float xv = g_x[gid];
    float hv = g_h[gid];
    float ov = g_oe[gid];
    o_in[gid]  = anchor ? xv : hv;
    o_out[gid] = anchor ? xv : ov;
}

// ---------------------------------------------------------------------------
__global__ __launch_bounds__(256) void gol_kernel(const float* __restrict__ src, int out_base)
{
    __shared__ float hn[24][257];
    __shared__ float nrm[24];
    __shared__ float red[256];
    const int tid = threadIdx.x;
    const size_t rowbase = (size_t)blockIdx.x * 25 + 1;
    for (int idx = tid; idx < 24 * 256; idx += 256) {
        int i = idx >> 8, k = idx & 255;
        hn[i][k] = src[(rowbase + i) * 256 + k];
    }
    __syncthreads();
    if (tid < 24) {
        float s = 0.f;
        for (int k = 0; k < 256; k++) { float v = hn[tid][k]; s += v * v; }
        nrm[tid] = 1.f / (sqrtf(s) + 1e-8f);
    }
    __syncthreads();
    for (int idx = tid; idx < 24 * 256; idx += 256) {
        int i = idx >> 8, k = idx & 255;
        hn[i][k] *= nrm[i];
    }
    __syncthreads();
    float local = 0.f;
    for (int p = tid; p < 276; p += 256) {
        int i = 0, pp = p;
        while (pp >= 23 - i) { pp -= 23 - i; i++; }
        int j = i + 1 + pp;
        float d = 0.f;
#pragma unroll 8
        for (int k = 0; k < 256; k++) d += hn[i][k] * hn[j][k];
        local += fabsf(d);
    }
    red[tid] = local;
    __syncthreads();
    for (int s = 128; s > 0; s >>= 1) {
        if (tid < s) red[tid] += red[tid + s];
        __syncthreads();
    }
    if (tid == 0) g_red[out_base + blockIdx.x] = red[0] * (2.f / (24.f * 23.f));
}

__global__ void gol_finalize(float* __restrict__ out)
{
    __shared__ double red[256];
    int tid = threadIdx.x;
    double s1 = 0.0, s2 = 0.0;
    for (int i = tid; i < CSTEPS * CB; i += 256) s1 += (double)g_red[i];
    for (int i = tid; i < CB; i += 256) s2 += (double)g_red[CSTEPS * CB + i];
    red[tid] = s1 / (double)(CSTEPS * CB) + s2 / (double)CB;
    __syncthreads();
    for (int s = 128; s > 0; s >>= 1) {
        if (tid < s) red[tid] += red[tid + s];
        __syncthreads();
    }
    if (tid == 0) out[0] = (float)red[0];
}

// ---------------------------------------------------------------------------
extern "C" void kernel_launch(void* const* d_in, const int* in_sizes, int n_in,
                              void* d_out, int out_size)
{
    (void)in_sizes; (void)n_in; (void)out_size;
    const float* emb  = (const float*)d_in[0];
    const float* Wmsg = (const float*)d_in[1];
    const float* Wih  = (const float*)d_in[2];
    const float* Whh  = (const float*)d_in[3];
    const float* Wout = (const float*)d_in[4];
    const int*   perm = (const int*)d_in[5];

    float* out = (float*)d_out;
    float* o_gol  = out;
    float* o_lstm = out + 1;
    float* o_in   = out + 1 + (size_t)CNH;
    float* o_out  = out + 1 + 2 * (size_t)CNH;
    float* o_hs   = out + 1 + 3 * (size_t)CNH;

    float *px, *ph, *pgx, *pm, *pt2, *pgates, *poe;
    cudaGetSymbolAddress((void**)&px,     g_x);
    cudaGetSymbolAddress((void**)&ph,     g_h);
    cudaGetSymbolAddress((void**)&pgx,    g_gx);
    cudaGetSymbolAddress((void**)&pm,     g_m);
    cudaGetSymbolAddress((void**)&pt2,    g_t2);
    cudaGetSymbolAddress((void**)&pgates, g_gates);
    cudaGetSymbolAddress((void**)&poe,    g_oe);

    prep_kernel<<<128, 256>>>(Wmsg);
    gather_init<<<CNH / 256, 256>>>(emb, perm, o_lstm);

    // gx = x @ W_ih[:, :256]^T  — chain prefix of t1, reused every step
    sgemm_nt<<<dim3(8, CN / 128), 256>>>(256, px, 256, Wih, 512,
                                         pgx, 1024, nullptr, nullptr);

    for (int s = 0; s < CSTEPS; s++) {
        // fused: t2 = h @ W_hh^T  AND  A = h @ W1^T  (both depend only on h)
        step_pre<<<1000, 256>>>(Whh, Wmsg);
        // per-edge exact msg chains (paired-k, 23 chains: i==j skipped)
        msg_exact<<<dim3(24, CB), 128>>>();
        // gates = chain(gx -> m terms) + t2   (post-add, commutative)
        sgemm_nt<<<dim3(8, CN / 128), 256>>>(256, pm, 256, Wih + 256, 512,
                                             pgates, 1024, pgx, pt2);
        lstm_step<<<CNH / 1024, 256>>>(o_hs + (size_t)s * CNH);
    }

    // output_embeddings = h_last @ W_out^T
    sgemm_nt<<<dim3(2, CN / 128), 256>>>(256, ph, 256, Wout, 256,
                                         poe, 256, nullptr, nullptr);
    finalize_emb<<<CNH / 256, 256>>>(o_in, o_out);

    gol_kernel<<<CSTEPS * CB, 256>>>(o_hs, 0);
    gol_kernel<<<CB, 256>>>(poe, CSTEPS * CB);
    gol_finalize<<<1, 256>>>(o_gol);
}